// round 13
// baseline (speedup 1.0000x reference)
#include <cuda_runtime.h>
#include <cuda.h>
#include <cuda_bf16.h>
#include <cstdint>
#include <cstdio>

// ============================================================================
// QuantizedLinear via two-digit int8 tcgen05 GEMM, persistent cluster-4.
//   out[t,o] = (sum_k x[t,k]*(w[o,k]-zp[o])) * scale[o] + bias[o]
//   M=TOKENS=4096, N=OUT_F=11008, K=IN_F=4096
//
// W int8-exact. x fixed-point per row: x ~= s_row*(128*h + l), h,l in s8.
// Two kind::i8 GEMMs (s32 in TMEM): D1 (cols 0-255), D0 (cols 256-511).
// out = (s_row*(128*D1+D0) - zp*rowsum)*scale + bias.
//
// Cluster (4,1,1): cg2 MMA pairs {0,1} and {2,3} compute the SAME 256 M-rows
// at ADJACENT N tiles. A (hi+lo) is shared: CTA0 multicasts its A rows to
// {0,2} (mask 0x5), CTA1 to {1,3} (mask 0xA) -> A LTS traffic halves.
// B loaded per-CTA (distinct per pair + cg2 row split). Follower warp-5
// forwards its FULL to the pair leader's AGG barrier; EMPTY (count=2) is
// released by BOTH pairs' commit-multicast(0xF) so the shared ring is safe.
// Ragged N (43 odd): last N-pair -> pair1 duplicates pair0's tile (benign).
// Warps: 0-3 epilogue, 4 producer, 5 driver (leaders) / forwarder (followers).
// ============================================================================

#define TOKENS 4096
#define IN_F   4096
#define OUT_F  11008

#define BN    256               // N per pair-tile
#define KC    64
#define NCH   (IN_F / KC)       // 64 chunks per tile
#define NST   9                 // pipeline stages
#define NCLUS 33                // 132 CTAs / 4 (cluster-4 active limit = 132)
#define NUNIT 352               // 16 M-pairs x 22 N-pairs

#if defined(__CUDA_ARCH__) && (defined(__CUDA_ARCH_FEAT_SM100_ALL) || defined(__CUDA_ARCH_FEAT_SM103_ALL) || defined(__CUDA_ARCH_FEAT_SM101_ALL))
#define HAVE_TCGEN05 1
#else
#define HAVE_TCGEN05 0
#endif

// ---- dynamic SMEM layout (per CTA) ----
#define OFF_TMEM     0
#define OFF_FULL(s)  (16 + 8*(s))     // 16..88
#define OFF_EMPTY(s) (96 + 8*(s))     // 96..168
#define OFF_AGG(s)   (176 + 8*(s))    // 176..248
#define OFF_DONE     256
#define OFF_EPIF     264
#define STAGE_STRIDE 24576            // AH 8K + AL 8K + B 8K (int8)
#define OFF_ST(s)    (1024 + (s)*STAGE_STRIDE)
#define ST_AH        0
#define ST_AL        8192
#define ST_B         16384
#define OFF_PRM      (1024 + NST*STAGE_STRIDE)   // 222208
#define SMEM_TOTAL   (OFF_PRM + 3*BN*4)          // 225280

// idesc kind::i8 cg2: c=S32(2)@[4:6), a=S8(1)@[7:10), b=S8(1)@[10:13),
// N/8 @[17:23), M_total/16 @[24:29)
#define MMA_IDESC ((2u<<4) | (1u<<7) | (1u<<10) | ((BN/8)<<17) | ((256/16)<<24))

// ---- scratch (device globals: no allocation allowed) ----
__device__ __align__(1024) int8_t g_W8[(size_t)OUT_F  * IN_F];
__device__ __align__(1024) int8_t g_Ah[(size_t)TOKENS * IN_F];
__device__ __align__(1024) int8_t g_Al[(size_t)TOKENS * IN_F];
__device__ float g_rowsum[TOKENS];
__device__ float g_rscale[TOKENS];

// ============================================================================
// Common helpers
// ============================================================================
__device__ __forceinline__ uint32_t smem_u32(const void* p) {
    uint32_t a;
    asm("{ .reg .u64 t; cvta.to.shared.u64 t, %1; cvt.u32.u64 %0, t; }"
        : "=r"(a) : "l"(p));
    return a;
}

// ============================================================================
// Fused preprocessing: blocks [0, NBLK_W) pack W; blocks [NBLK_W, +TOKENS)
// do per-row two-digit quantization of x (+ rowsum/rowscale).
// ============================================================================
#define NBLK_W ((OUT_F * IN_F / 4) / 256)   // 44032

__global__ void k_prep(const int4* __restrict__ w4, char4* __restrict__ W,
                       const float4* __restrict__ x4,
                       char4* __restrict__ hi, char4* __restrict__ lo,
                       float* __restrict__ rs, float* __restrict__ rsc) {
    __shared__ float redM[8], redS[8], bc[1];
    const int tid = threadIdx.x;
    if (blockIdx.x < NBLK_W) {
        const int i = blockIdx.x * 256 + tid;
        int4 v = w4[i];
        W[i] = make_char4((signed char)v.x, (signed char)v.y,
                          (signed char)v.z, (signed char)v.w);
        return;
    }
    const int row = blockIdx.x - NBLK_W;
    const float4* px = x4 + (size_t)row * (IN_F / 4);
    float mx = 0.f, sm = 0.f;
    for (int i = tid; i < IN_F / 4; i += 256) {
        float4 v = px[i];
        mx = fmaxf(mx, fmaxf(fmaxf(fabsf(v.x), fabsf(v.y)),
                             fmaxf(fabsf(v.z), fabsf(v.w))));
        sm += v.x + v.y + v.z + v.w;
    }
#pragma unroll
    for (int o = 16; o > 0; o >>= 1) {
        mx = fmaxf(mx, __shfl_xor_sync(0xffffffffu, mx, o));
        sm += __shfl_xor_sync(0xffffffffu, sm, o);
    }
    if ((tid & 31) == 0) { redM[tid >> 5] = mx; redS[tid >> 5] = sm; }
    __syncthreads();
    if (tid < 8) {
        float m = redM[tid], s = redS[tid];
#pragma unroll
        for (int o = 4; o > 0; o >>= 1) {
            m = fmaxf(m, __shfl_xor_sync(0xffu, m, o));
            s += __shfl_xor_sync(0xffu, s, o);
        }
        if (tid == 0) {
            bc[0]    = (m > 1e-30f) ? (16000.f / m) : 0.f;   // inv scale
            rs[row]  = s;
            rsc[row] = (m > 1e-30f) ? (m / 16000.f) : 0.f;
        }
    }
    __syncthreads();
    const float inv = bc[0];
    char4* ph = hi + (size_t)row * (IN_F / 4);
    char4* pl = lo + (size_t)row * (IN_F / 4);
    for (int i = tid; i < IN_F / 4; i += 256) {
        float4 v = px[i];
        const float* f = &v.x;
        signed char hd[4], ld[4];
#pragma unroll
        for (int j = 0; j < 4; j++) {
            int vq = __float2int_rn(f[j] * inv);   // |vq| <= 16000
            int h  = (vq + 64) >> 7;               // |h| <= 126
            int l  = vq - (h << 7);                // in [-64, 63]
            hd[j] = (signed char)h;
            ld[j] = (signed char)l;
        }
        ph[i] = make_char4(hd[0], hd[1], hd[2], hd[3]);
        pl[i] = make_char4(ld[0], ld[1], ld[2], ld[3]);
    }
}

// ============================================================================
// tcgen05 PTX helpers (guarded)
// ============================================================================
#if HAVE_TCGEN05
#define MBAR_INIT(addr, cnt) \
    asm volatile("mbarrier.init.shared.b64 [%0], %1;" :: "r"(addr), "r"((uint32_t)(cnt)) : "memory")
#define MBAR_EXPECT(addr, bytes) \
    asm volatile("mbarrier.arrive.expect_tx.shared.b64 _, [%0], %1;" :: "r"(addr), "r"((uint32_t)(bytes)) : "memory")

__device__ __forceinline__ void mbar_wait(uint32_t addr, uint32_t parity) {
    uint32_t done;
    asm volatile(
        "{\n\t.reg .pred p;\n\t"
        "mbarrier.try_wait.parity.acquire.cta.shared::cta.b64 p, [%1], %2;\n\t"
        "selp.b32 %0, 1, 0, p;\n\t}"
        : "=r"(done) : "r"(addr), "r"(parity) : "memory");
    if (!done) {
        asm volatile(
            "{\n\t.reg .pred P1;\n\t"
            "WL_%=:\n\t"
            "mbarrier.try_wait.parity.acquire.cta.shared::cta.b64 P1, [%0], %1, 0x989680;\n\t"
            "@P1 bra.uni WD_%=;\n\t"
            "bra.uni WL_%=;\n\t"
            "WD_%=:\n\t}"
            :: "r"(addr), "r"(parity) : "memory");
    }
}

// relaxed wait: ONLY for waits whose post-wait SMEM accesses are async-proxy
__device__ __forceinline__ void mbar_wait_relaxed(uint32_t addr, uint32_t parity) {
    uint32_t done;
    asm volatile(
        "{\n\t.reg .pred p;\n\t"
        "mbarrier.try_wait.parity.relaxed.cta.shared::cta.b64 p, [%1], %2;\n\t"
        "selp.b32 %0, 1, 0, p;\n\t}"
        : "=r"(done) : "r"(addr), "r"(parity) : "memory");
    if (!done) {
        asm volatile(
            "{\n\t.reg .pred P1;\n\t"
            "RL_%=:\n\t"
            "mbarrier.try_wait.parity.relaxed.cta.shared::cta.b64 P1, [%0], %1, 0x989680;\n\t"
            "@P1 bra.uni RD_%=;\n\t"
            "bra.uni RL_%=;\n\t"
            "RD_%=:\n\t}"
            :: "r"(addr), "r"(parity) : "memory");
    }
}

// plain local TMA 3D load (complete_tx to this CTA's barrier)
__device__ __forceinline__ void tma_ld_local(uint32_t smem, const void* map,
                                             int x, int y, uint32_t mbar) {
    asm volatile(
        "cp.async.bulk.tensor.3d.shared::cta.global.tile.mbarrier::complete_tx::bytes "
        "[%0], [%1, {%2, %3, %4}], [%5];"
        :: "r"(smem), "l"(map), "r"(x), "r"(y), "r"(0), "r"(mbar) : "memory");
}

// multicast TMA 3D load: data + complete_tx delivered to the same SMEM offset
// in every CTA whose bit is set in mask.
__device__ __forceinline__ void tma_ld_mc(uint32_t smem, const void* map,
                                          int x, int y, uint32_t mbar,
                                          uint16_t mask) {
    asm volatile(
        "cp.async.bulk.tensor.3d.shared::cluster.global.tile"
        ".mbarrier::complete_tx::bytes.multicast::cluster "
        "[%0], [%1, {%2, %3, %4}], [%5], %6;"
        :: "r"(smem), "l"(map), "r"(x), "r"(y), "r"(0), "r"(mbar), "h"(mask)
        : "memory");
}

// K-major SW64 smem descriptor: layout=4 (SW64), version=1, SBO=32, LBO=1
__device__ __forceinline__ uint64_t mk_desc64(uint32_t addr) {
    const uint64_t BASE = (4ull << 61) | (1ull << 46) | (32ull << 32) | (1ull << 16);
    return BASE | ((uint64_t)(addr >> 4) & 0x3FFF);
}

__device__ __forceinline__ void mma_i8_ss_cg2(uint32_t d, uint64_t a, uint64_t b,
                                              uint32_t idesc, uint32_t en) {
    asm volatile(
        "{\n\t.reg .pred p;\n\t"
        "setp.ne.u32 p, %4, 0;\n\t"
        "tcgen05.mma.cta_group::2.kind::i8 [%0], %1, %2, %3, "
        "{%5, %5, %5, %5, %5, %5, %5, %5}, p;\n\t}"
        :: "r"(d), "l"(a), "l"(b), "r"(idesc), "r"(en), "r"(0u) : "memory");
}

__device__ __forceinline__ void tc_commit_mc(uint32_t mbar, uint16_t mask) {
    asm volatile(
        "tcgen05.commit.cta_group::2.mbarrier::arrive::one.shared::cluster"
        ".multicast::cluster.b64 [%0], %1;"
        :: "r"(mbar), "h"(mask) : "memory");
}

// arrive on a target cluster rank's mbarrier at the same smem offset
__device__ __forceinline__ void mbar_arrive_rank(uint32_t addr, int trank) {
    asm volatile(
        "{\n\t.reg .b32 ra;\n\t"
        "mapa.shared::cluster.u32 ra, %0, %1;\n\t"
        "mbarrier.arrive.shared::cluster.b64 _, [ra];\n\t}"
        :: "r"(addr), "r"(trank) : "memory");
}

#define TC_LD_X32(r, tmem_addr) \
    asm volatile( \
        "tcgen05.ld.sync.aligned.32x32b.x32.b32 " \
        "{%0, %1, %2, %3, %4, %5, %6, %7, " \
        " %8, %9, %10, %11, %12, %13, %14, %15, " \
        " %16, %17, %18, %19, %20, %21, %22, %23, " \
        " %24, %25, %26, %27, %28, %29, %30, %31}, [%32];" \
        : "=r"((r)[0]),  "=r"((r)[1]),  "=r"((r)[2]),  "=r"((r)[3]), \
          "=r"((r)[4]),  "=r"((r)[5]),  "=r"((r)[6]),  "=r"((r)[7]), \
          "=r"((r)[8]),  "=r"((r)[9]),  "=r"((r)[10]), "=r"((r)[11]), \
          "=r"((r)[12]), "=r"((r)[13]), "=r"((r)[14]), "=r"((r)[15]), \
          "=r"((r)[16]), "=r"((r)[17]), "=r"((r)[18]), "=r"((r)[19]), \
          "=r"((r)[20]), "=r"((r)[21]), "=r"((r)[22]), "=r"((r)[23]), \
          "=r"((r)[24]), "=r"((r)[25]), "=r"((r)[26]), "=r"((r)[27]), \
          "=r"((r)[28]), "=r"((r)[29]), "=r"((r)[30]), "=r"((r)[31]) \
        : "r"(tmem_addr))

#define CLUSTER_SYNC_() do { \
    asm volatile("barrier.cluster.arrive.aligned;" ::: "memory"); \
    asm volatile("barrier.cluster.wait.aligned;" ::: "memory"); \
} while (0)
#endif  // HAVE_TCGEN05

// ============================================================================
// Persistent GEMM kernel: 33 clusters of 4 CTAs; cluster cl owns units
// u = cl + ui*33; unit u: M-pair mp = u & 15, N-pair np = u >> 4;
// pair p computes N-tile nt = min(2*np + p, 42) (dup on ragged last pair).
// ============================================================================
__global__ void __launch_bounds__(192, 1) __cluster_dims__(4, 1, 1) qlinear_tc(
    const __grid_constant__ CUtensorMap tmAh,
    const __grid_constant__ CUtensorMap tmAl,
    const __grid_constant__ CUtensorMap tmB,
    const float* __restrict__ scales,
    const float* __restrict__ zps,
    const float* __restrict__ biasv,
    const float* __restrict__ rowsum,
    const float* __restrict__ rscale,
    float* __restrict__ out)
{
#if HAVE_TCGEN05
    extern __shared__ __align__(1024) char smem[];
    const uint32_t sb = smem_u32(smem);
    const int tid  = threadIdx.x;
    const int wid  = tid >> 5;
    const int lane = tid & 31;
    const int rank   = blockIdx.x & 3;     // cluster rank 0..3
    const int cl     = blockIdx.x >> 2;    // cluster id 0..32
    const int pairid = rank >> 1;          // cg2 pair 0 / 1
    const int prank  = rank & 1;           // rank within pair
    const int nunits = (NUNIT - cl + NCLUS - 1) / NCLUS;

    if (wid == 0) {
        asm volatile("tcgen05.alloc.cta_group::2.sync.aligned.shared::cta.b32 [%0], %1;"
                     :: "r"(sb + OFF_TMEM), "r"(512u) : "memory");
        asm volatile("tcgen05.relinquish_alloc_permit.cta_group::2.sync.aligned;");
    }
    if (tid == 0) {
        for (int s = 0; s < NST; s++) {
            MBAR_INIT(sb + OFF_FULL(s), 1);
            MBAR_INIT(sb + OFF_EMPTY(s), 2);   // commits from BOTH pair drivers
            MBAR_INIT(sb + OFF_AGG(s), 1);     // follower's forward arrive
        }
        MBAR_INIT(sb + OFF_DONE, 1);
        MBAR_INIT(sb + OFF_EPIF, 2);           // one arrive per pair CTA epilogue
        asm volatile("fence.proxy.async.shared::cta;" ::: "memory");
    }
    __syncthreads();
    CLUSTER_SYNC_();   // all cluster barriers live before multicast TMA/commits

    uint32_t tmem;
    asm volatile("ld.shared.b32 %0, [%1];" : "=r"(tmem) : "r"(sb + OFF_TMEM));

    // ---------------- producer warp (warp 4, lane 0, ALL CTAs) ----------------
    if (wid == 4 && lane == 0) {
        const uint16_t amask = (rank == 0) ? 0x5 : 0xA;   // {0,2} or {1,3}
        int s = 0, k = 0;
        for (int ui = 0; ui < nunits; ui++) {
            const int u  = cl + ui * NCLUS;
            const int mp = u & 15, np = u >> 4;
            const int nt = min(2 * np + pairid, 42);
            const int rb = mp * 256 + prank * 128;        // A rows (this CTA)
            const int cb = nt * 256 + prank * 128;        // B rows (this CTA)
            for (int c = 0; c < NCH; c++) {
                if (k > 0) mbar_wait_relaxed(sb + OFF_EMPTY(s), (k - 1) & 1);
                MBAR_EXPECT(sb + OFF_FULL(s), (uint32_t)STAGE_STRIDE);
                const uint32_t st = sb + OFF_ST(s);
                const uint32_t fb = sb + OFF_FULL(s);
                tma_ld_local(st + ST_B, &tmB, c * KC, cb, fb);
                if (rank < 2) {   // A issued once per multicast group
                    tma_ld_mc(st + ST_AH, &tmAh, c * KC, rb, fb, amask);
                    tma_ld_mc(st + ST_AL, &tmAl, c * KC, rb, fb, amask);
                }
                if (++s == NST) { s = 0; k++; }
            }
        }
    }

    // ---------------- warp 5 lane 0: driver (leaders) / forwarder -------------
    if (wid == 5 && lane == 0) {
        if (prank == 0) {
            // MMA driver (cluster ranks 0 and 2)
            const uint16_t dmask = (uint16_t)(0x3 << (pairid * 2));
            int s = 0, k = 0;
            for (int ui = 0; ui < nunits; ui++) {
                if (ui > 0) {
                    mbar_wait(sb + OFF_EPIF, (ui - 1) & 1);
                    asm volatile("tcgen05.fence::after_thread_sync;" ::: "memory");
                }
                for (int c = 0; c < NCH; c++) {
                    mbar_wait_relaxed(sb + OFF_FULL(s), k & 1);  // own CTA full
                    mbar_wait(sb + OFF_AGG(s), k & 1);           // peer CTA full
                    const uint32_t st = sb + OFF_ST(s);
                    const uint64_t ah = mk_desc64(st + ST_AH);
                    const uint64_t al = mk_desc64(st + ST_AL);
                    const uint64_t bd = mk_desc64(st + ST_B);
                    const uint32_t en0 = (c > 0) ? 1u : 0u;
                    mma_i8_ss_cg2(tmem,       ah,     bd,     MMA_IDESC, en0);
                    mma_i8_ss_cg2(tmem,       ah + 2, bd + 2, MMA_IDESC, 1u);
                    mma_i8_ss_cg2(tmem + 256, al,     bd,     MMA_IDESC, en0);
                    mma_i8_ss_cg2(tmem + 256, al + 2, bd + 2, MMA_IDESC, 1u);
                    tc_commit_mc(sb + OFF_EMPTY(s), 0xF);   // release in ALL 4 CTAs
                    if (c == NCH - 1) tc_commit_mc(sb + OFF_DONE, dmask);
                    if (++s == NST) { s = 0; k++; }
                }
            }
        } else {
            // FULL forwarder (cluster ranks 1 and 3) -> pair leader's AGG
            int s = 0, k = 0;
            for (int ui = 0; ui < nunits; ui++) {
                for (int c = 0; c < NCH; c++) {
                    mbar_wait(sb + OFF_FULL(s), k & 1);
                    mbar_arrive_rank(sb + OFF_AGG(s), rank - 1);
                    if (++s == NST) { s = 0; k++; }
                }
            }
        }
    }

    // ---------------- epilogue warps (warps 0-3, ALL CTAs) --------------------
    if (wid < 4) {
        float* s_sc = (float*)(smem + OFF_PRM);
        float* s_zp = s_sc + BN;
        float* s_bi = s_zp + BN;
        const int lrank = rank & ~1;   // pair leader's cluster rank
        for (int ui = 0; ui < nunits; ui++) {
            const int u  = cl + ui * NCLUS;
            const int mp = u & 15, np = u >> 4;
            const int nt = min(2 * np + pairid, 42);
            const int cb = nt * 256;
            const int row = mp * 256 + prank * 128 + wid * 32 + lane;
            for (int i = tid; i < BN; i += 128) {
                s_sc[i] = scales[cb + i];
                s_zp[i] = zps[cb + i];
                s_bi[i] = biasv[cb + i];
            }
            asm volatile("bar.sync 1, 128;" ::: "memory");

            mbar_wait(sb + OFF_DONE, ui & 1);
            asm volatile("tcgen05.fence::after_thread_sync;" ::: "memory");

            const float rs  = rowsum[row];
            const float srw = rscale[row];
            float* orow = out + (size_t)row * OUT_F + cb;

            // double-buffered TMEM drain; EPIF released right after last read
            uint32_t r1a[32], r0a[32], r1b[32], r0b[32];
            TC_LD_X32(r1a, tmem);
            TC_LD_X32(r0a, tmem + 256);
#pragma unroll
            for (int blk = 0; blk < 8; blk++) {
                asm volatile("tcgen05.wait::ld.sync.aligned;" ::: "memory");
                if (blk < 7) {
                    uint32_t* R1n = (blk & 1) ? r1a : r1b;
                    uint32_t* R0n = (blk & 1) ? r0a : r0b;
                    TC_LD_X32(R1n, tmem + (blk + 1) * 32);
                    TC_LD_X32(R0n, tmem + 256 + (blk + 1) * 32);
                } else {
                    asm volatile("tcgen05.fence::before_thread_sync;" ::: "memory");
                    asm volatile("bar.sync 2, 128;" ::: "memory");
                    if (tid == 0) mbar_arrive_rank(sb + OFF_EPIF, lrank);
                }
                const uint32_t* R1 = (blk & 1) ? r1b : r1a;
                const uint32_t* R0 = (blk & 1) ? r0b : r0a;
#pragma unroll
                for (int c = 0; c < 32; c += 4) {
                    const int col = blk * 32 + c;
                    float4 v;
#pragma unroll
                    for (int j = 0; j < 4; j++) {
                        const float acc = fmaf(128.f, (float)(int)R1[c + j],
                                               (float)(int)R0[c + j]);
                        (&v.x)[j] = (srw * acc - s_zp[col + j] * rs) * s_sc[col + j]
                                    + s_bi[col + j];
                    }
                    *reinterpret_cast<float4*>(orow + col) = v;
                }
            }
            asm volatile("bar.sync 1, 128;" ::: "memory");
        }
    }

    __syncthreads();
    CLUSTER_SYNC_();   // all CTAs done (incl. in-flight multicasts) before dealloc
    if (wid == 0) {
        asm volatile("tcgen05.dealloc.cta_group::2.sync.aligned.b32 %0, %1;"
                     :: "r"(tmem), "r"(512u));
    }
    CLUSTER_SYNC_();
#else
    (void)tmAh; (void)tmAl; (void)tmB; (void)scales; (void)zps; (void)biasv;
    (void)rowsum; (void)rscale; (void)out;
#endif
}

// ============================================================================
// Host launcher
// ============================================================================
typedef CUresult (*tme_fn_t)(CUtensorMap*, CUtensorMapDataType, cuuint32_t, void*,
                             const cuuint64_t*, const cuuint64_t*,
                             const cuuint32_t*, const cuuint32_t*,
                             CUtensorMapInterleave, CUtensorMapSwizzle,
                             CUtensorMapL2promotion, CUtensorMapFloatOOBfill);

extern "C" void kernel_launch(void* const* d_in, const int* in_sizes, int n_in,
                              void* d_out, int out_size) {
    const float* input  = (const float*)d_in[0];
    const int*   w      = (const int*)d_in[1];
    const float* scales = (const float*)d_in[2];
    const float* zps    = (const float*)d_in[3];
    const float* bias   = (const float*)d_in[4];
    float* out = (float*)d_out;
    (void)in_sizes; (void)n_in; (void)out_size;

    void *pW = nullptr, *pAh = nullptr, *pAl = nullptr, *pRs = nullptr, *pSc = nullptr;
    cudaGetSymbolAddress(&pW,  g_W8);
    cudaGetSymbolAddress(&pAh, g_Ah);
    cudaGetSymbolAddress(&pAl, g_Al);
    cudaGetSymbolAddress(&pRs, g_rowsum);
    cudaGetSymbolAddress(&pSc, g_rscale);

    tme_fn_t encode = nullptr;
    cudaDriverEntryPointQueryResult qr;
    cudaGetDriverEntryPoint("cuTensorMapEncodeTiled", (void**)&encode,
                            cudaEnableDefault, &qr);

    CUtensorMap mAh, mAl, mB;
    __builtin_memset(&mAh, 0, sizeof(mAh));
    __builtin_memset(&mAl, 0, sizeof(mAl));
    __builtin_memset(&mB, 0, sizeof(mB));
    if (encode) {
        {
            cuuint64_t dims[3]    = { IN_F, TOKENS, 1 };
            cuuint64_t strides[2] = { IN_F, (cuuint64_t)IN_F * TOKENS };
            cuuint32_t box[3]     = { KC, 128, 1 };    // 64B rows (SW64)
            cuuint32_t es[3]      = { 1, 1, 1 };
            encode(&mAh, CU_TENSOR_MAP_DATA_TYPE_UINT8, 3, pAh, dims, strides, box, es,
                   CU_TENSOR_MAP_INTERLEAVE_NONE, CU_TENSOR_MAP_SWIZZLE_64B,
                   CU_TENSOR_MAP_L2_PROMOTION_L2_128B, CU_TENSOR_MAP_FLOAT_OOB_FILL_NONE);
            encode(&mAl, CU_TENSOR_MAP_DATA_TYPE_UINT8, 3, pAl, dims, strides, box, es,
                   CU_TENSOR_MAP_INTERLEAVE_NONE, CU_TENSOR_MAP_SWIZZLE_64B,
                   CU_TENSOR_MAP_L2_PROMOTION_L2_128B, CU_TENSOR_MAP_FLOAT_OOB_FILL_NONE);
        }
        {
            cuuint64_t dims[3]    = { IN_F, OUT_F, 1 };
            cuuint64_t strides[2] = { IN_F, (cuuint64_t)IN_F * OUT_F };
            cuuint32_t box[3]     = { KC, 128, 1 };    // 128-row pieces per CTA
            cuuint32_t es[3]      = { 1, 1, 1 };
            encode(&mB, CU_TENSOR_MAP_DATA_TYPE_UINT8, 3, pW, dims, strides, box, es,
                   CU_TENSOR_MAP_INTERLEAVE_NONE, CU_TENSOR_MAP_SWIZZLE_64B,
                   CU_TENSOR_MAP_L2_PROMOTION_L2_128B, CU_TENSOR_MAP_FLOAT_OOB_FILL_NONE);
        }
    }

    cudaFuncSetAttribute(qlinear_tc, cudaFuncAttributeMaxDynamicSharedMemorySize,
                         SMEM_TOTAL);

    // fused preprocessing: W pack + x two-digit quantization (overlapped)
    k_prep<<<NBLK_W + TOKENS, 256>>>((const int4*)w, (char4*)pW,
                                     (const float4*)input, (char4*)pAh, (char4*)pAl,
                                     (float*)pRs, (float*)pSc);

    // persistent GEMM: 132 CTAs = 33 clusters of 4 (cluster-4 active limit)
    qlinear_tc<<<dim3(4 * NCLUS, 1), 192, SMEM_TOTAL>>>(
        mAh, mAl, mB, scales, zps, bias,
        (const float*)pRs, (const float*)pSc, out);
}

// round 15
// speedup vs baseline: 1.0851x; 1.0851x over previous
#include <cuda_runtime.h>
#include <cuda.h>
#include <cuda_bf16.h>
#include <cstdint>
#include <cstdio>

// ============================================================================
// QuantizedLinear via two-digit int8 tcgen05 GEMM, persistent cg2 clusters,
// DYNAMIC work-stealing over 256x256 tiles.
//   out[t,o] = (sum_k x[t,k]*(w[o,k]-zp[o])) * scale[o] + bias[o]
//   M=TOKENS=4096, N=OUT_F=11008, K=IN_F=4096
//
// W int8-exact. x fixed-point per row: x ~= s_row*(128*h + l), h,l in s8.
// Two kind::i8 GEMMs (s32 in TMEM): D1 (cols 0-255), D0 (cols 256-511).
// out = (s_row*(128*D1+D0) - zp*rowsum)*scale + bias.
//
// 74 cg2 pairs steal units from a global ticket (reset by k_prep each launch).
// Leader-producer fetches u, publishes via UINFO + UNIT barriers (cluster
// release/acquire); URD (count=4) guards slot reuse. Sentinel -1 terminates.
// Continuous 9-stage TMA ring across tiles; epilogue double-buffered LDTM
// drain releases EPI_FREE right after reads so next tile's MMA overlaps tail.
// Warps: 0-3 epilogue, 4 producer (both CTAs), 5 MMA driver (leader).
// ============================================================================

#define TOKENS 4096
#define IN_F   4096
#define OUT_F  11008

#define BN    256               // N per pair-tile (one N=256 MMA region)
#define KC    64
#define NCH   (IN_F / KC)       // 64 chunks per tile
#define NST   9                 // pipeline stages
#define NPAIR 74
#define NUNIT 688               // 16 M-pairs x 43 N-tiles

#if defined(__CUDA_ARCH__) && (defined(__CUDA_ARCH_FEAT_SM100_ALL) || defined(__CUDA_ARCH_FEAT_SM103_ALL) || defined(__CUDA_ARCH_FEAT_SM101_ALL))
#define HAVE_TCGEN05 1
#else
#define HAVE_TCGEN05 0
#endif

// ---- dynamic SMEM layout (per CTA) ----
#define OFF_TMEM     0
#define OFF_FULL(s)  (16 + 8*(s))     // 16..88
#define OFF_EMPTY(s) (96 + 8*(s))     // 96..168
#define OFF_DONE     176
#define OFF_EPIF     184
#define OFF_UNITB(s) (192 + 8*(s))    // 192, 200
#define OFF_URD(s)   (208 + 8*(s))    // 208, 216
#define OFF_UINFO(s) (224 + 4*(s))    // 224, 228 (int)
#define STAGE_STRIDE 24576            // AH 8K + AL 8K + B 8K (int8)
#define OFF_ST(s)    (1024 + (s)*STAGE_STRIDE)
#define ST_AH        0
#define ST_AL        8192
#define ST_B         16384
#define OFF_PRM      (1024 + NST*STAGE_STRIDE)   // 222208
#define SMEM_TOTAL   (OFF_PRM + 3*BN*4)          // 225280

// idesc kind::i8 cg2: c=S32(2)@[4:6), a=S8(1)@[7:10), b=S8(1)@[10:13),
// N/8 @[17:23), M_total/16 @[24:29)
#define MMA_IDESC ((2u<<4) | (1u<<7) | (1u<<10) | ((BN/8)<<17) | ((256/16)<<24))

// ---- scratch (device globals: no allocation allowed) ----
__device__ __align__(1024) int8_t g_W8[(size_t)OUT_F  * IN_F];
__device__ __align__(1024) int8_t g_Ah[(size_t)TOKENS * IN_F];
__device__ __align__(1024) int8_t g_Al[(size_t)TOKENS * IN_F];
__device__ float g_rowsum[TOKENS];
__device__ float g_rscale[TOKENS];
__device__ int   g_ticket;             // reset by k_prep every launch

// ============================================================================
// Common helpers
// ============================================================================
__device__ __forceinline__ uint32_t smem_u32(const void* p) {
    uint32_t a;
    asm("{ .reg .u64 t; cvta.to.shared.u64 t, %1; cvt.u32.u64 %0, t; }"
        : "=r"(a) : "l"(p));
    return a;
}

// ============================================================================
// Fused preprocessing: blocks [0, NBLK_W) pack W; blocks [NBLK_W, +TOKENS)
// do per-row two-digit quantization of x (+ rowsum/rowscale). Row-0 block
// also resets the work-steal ticket.
// ============================================================================
#define NBLK_W ((OUT_F * IN_F / 4) / 256)   // 44032

__global__ void k_prep(const int4* __restrict__ w4, char4* __restrict__ W,
                       const float4* __restrict__ x4,
                       char4* __restrict__ hi, char4* __restrict__ lo,
                       float* __restrict__ rs, float* __restrict__ rsc) {
    __shared__ float redM[8], redS[8], bc[1];
    const int tid = threadIdx.x;
    if (blockIdx.x < NBLK_W) {
        const int i = blockIdx.x * 256 + tid;
        int4 v = w4[i];
        W[i] = make_char4((signed char)v.x, (signed char)v.y,
                          (signed char)v.z, (signed char)v.w);
        return;
    }
    const int row = blockIdx.x - NBLK_W;
    if (row == 0 && tid == 0) g_ticket = 0;     // reset work-steal pool
    const float4* px = x4 + (size_t)row * (IN_F / 4);
    float mx = 0.f, sm = 0.f;
    for (int i = tid; i < IN_F / 4; i += 256) {
        float4 v = px[i];
        mx = fmaxf(mx, fmaxf(fmaxf(fabsf(v.x), fabsf(v.y)),
                             fmaxf(fabsf(v.z), fabsf(v.w))));
        sm += v.x + v.y + v.z + v.w;
    }
#pragma unroll
    for (int o = 16; o > 0; o >>= 1) {
        mx = fmaxf(mx, __shfl_xor_sync(0xffffffffu, mx, o));
        sm += __shfl_xor_sync(0xffffffffu, sm, o);
    }
    if ((tid & 31) == 0) { redM[tid >> 5] = mx; redS[tid >> 5] = sm; }
    __syncthreads();
    if (tid < 8) {
        float m = redM[tid], s = redS[tid];
#pragma unroll
        for (int o = 4; o > 0; o >>= 1) {
            m = fmaxf(m, __shfl_xor_sync(0xffu, m, o));
            s += __shfl_xor_sync(0xffu, s, o);
        }
        if (tid == 0) {
            bc[0]    = (m > 1e-30f) ? (16000.f / m) : 0.f;   // inv scale
            rs[row]  = s;
            rsc[row] = (m > 1e-30f) ? (m / 16000.f) : 0.f;
        }
    }
    __syncthreads();
    const float inv = bc[0];
    char4* ph = hi + (size_t)row * (IN_F / 4);
    char4* pl = lo + (size_t)row * (IN_F / 4);
    for (int i = tid; i < IN_F / 4; i += 256) {
        float4 v = px[i];
        const float* f = &v.x;
        signed char hd[4], ld[4];
#pragma unroll
        for (int j = 0; j < 4; j++) {
            int vq = __float2int_rn(f[j] * inv);   // |vq| <= 16000
            int h  = (vq + 64) >> 7;               // |h| <= 126
            int l  = vq - (h << 7);                // in [-64, 63]
            hd[j] = (signed char)h;
            ld[j] = (signed char)l;
        }
        ph[i] = make_char4(hd[0], hd[1], hd[2], hd[3]);
        pl[i] = make_char4(ld[0], ld[1], ld[2], ld[3]);
    }
}

// ============================================================================
// tcgen05 PTX helpers (guarded)
// ============================================================================
#if HAVE_TCGEN05
#define MBAR_INIT(addr, cnt) \
    asm volatile("mbarrier.init.shared.b64 [%0], %1;" :: "r"(addr), "r"((uint32_t)(cnt)) : "memory")
#define MBAR_EXPECT(addr, bytes) \
    asm volatile("mbarrier.arrive.expect_tx.shared.b64 _, [%0], %1;" :: "r"(addr), "r"((uint32_t)(bytes)) : "memory")

__device__ __forceinline__ void mbar_wait(uint32_t addr, uint32_t parity) {
    uint32_t done;
    asm volatile(
        "{\n\t.reg .pred p;\n\t"
        "mbarrier.try_wait.parity.acquire.cta.shared::cta.b64 p, [%1], %2;\n\t"
        "selp.b32 %0, 1, 0, p;\n\t}"
        : "=r"(done) : "r"(addr), "r"(parity) : "memory");
    if (!done) {
        asm volatile(
            "{\n\t.reg .pred P1;\n\t"
            "WL_%=:\n\t"
            "mbarrier.try_wait.parity.acquire.cta.shared::cta.b64 P1, [%0], %1, 0x989680;\n\t"
            "@P1 bra.uni WD_%=;\n\t"
            "bra.uni WL_%=;\n\t"
            "WD_%=:\n\t}"
            :: "r"(addr), "r"(parity) : "memory");
    }
}

// cluster-scope acquire wait (for data released by cluster-scope arrives)
__device__ __forceinline__ void mbar_wait_cl(uint32_t addr, uint32_t parity) {
    uint32_t done;
    asm volatile(
        "{\n\t.reg .pred p;\n\t"
        "mbarrier.try_wait.parity.acquire.cluster.shared::cta.b64 p, [%1], %2;\n\t"
        "selp.b32 %0, 1, 0, p;\n\t}"
        : "=r"(done) : "r"(addr), "r"(parity) : "memory");
    if (!done) {
        asm volatile(
            "{\n\t.reg .pred P1;\n\t"
            "CL_%=:\n\t"
            "mbarrier.try_wait.parity.acquire.cluster.shared::cta.b64 P1, [%0], %1, 0x989680;\n\t"
            "@P1 bra.uni CD_%=;\n\t"
            "bra.uni CL_%=;\n\t"
            "CD_%=:\n\t}"
            :: "r"(addr), "r"(parity) : "memory");
    }
}

// relaxed wait: ONLY for waits whose post-wait SMEM accesses are async-proxy
__device__ __forceinline__ void mbar_wait_relaxed(uint32_t addr, uint32_t parity) {
    uint32_t done;
    asm volatile(
        "{\n\t.reg .pred p;\n\t"
        "mbarrier.try_wait.parity.relaxed.cta.shared::cta.b64 p, [%1], %2;\n\t"
        "selp.b32 %0, 1, 0, p;\n\t}"
        : "=r"(done) : "r"(addr), "r"(parity) : "memory");
    if (!done) {
        asm volatile(
            "{\n\t.reg .pred P1;\n\t"
            "RL_%=:\n\t"
            "mbarrier.try_wait.parity.relaxed.cta.shared::cta.b64 P1, [%0], %1, 0x989680;\n\t"
            "@P1 bra.uni RD_%=;\n\t"
            "bra.uni RL_%=;\n\t"
            "RD_%=:\n\t}"
            :: "r"(addr), "r"(parity) : "memory");
    }
}

// cg2 TMA 3D load: both CTAs execute; complete_tx targets leader CTA's barrier
// via Sm100MmaPeerBitMask (clear bit 24 of the local barrier address).
__device__ __forceinline__ void tma_ld_cg2(uint32_t smem, const void* map,
                                           int x, int y, uint32_t mbar) {
    asm volatile(
        "{\n\t.reg .b32 lb;\n\t"
        "and.b32 lb, %5, 0xFEFFFFFF;\n\t"
        "cp.async.bulk.tensor.3d.cta_group::2.shared::cluster.global"
        ".tile.mbarrier::complete_tx::bytes [%0], [%1, {%2, %3, %4}], [lb];\n\t}"
        :: "r"(smem), "l"(map), "r"(x), "r"(y), "r"(0), "r"(mbar) : "memory");
}

// K-major SW64 smem descriptor: layout=4 (SW64), version=1, SBO=32, LBO=1
__device__ __forceinline__ uint64_t mk_desc64(uint32_t addr) {
    const uint64_t BASE = (4ull << 61) | (1ull << 46) | (32ull << 32) | (1ull << 16);
    return BASE | ((uint64_t)(addr >> 4) & 0x3FFF);
}

__device__ __forceinline__ void mma_i8_ss_cg2(uint32_t d, uint64_t a, uint64_t b,
                                              uint32_t idesc, uint32_t en) {
    asm volatile(
        "{\n\t.reg .pred p;\n\t"
        "setp.ne.u32 p, %4, 0;\n\t"
        "tcgen05.mma.cta_group::2.kind::i8 [%0], %1, %2, %3, "
        "{%5, %5, %5, %5, %5, %5, %5, %5}, p;\n\t}"
        :: "r"(d), "l"(a), "l"(b), "r"(idesc), "r"(en), "r"(0u) : "memory");
}

__device__ __forceinline__ void tc_commit_mc2(uint32_t mbar) {
    asm volatile(
        "tcgen05.commit.cta_group::2.mbarrier::arrive::one.shared::cluster"
        ".multicast::cluster.b64 [%0], %1;"
        :: "r"(mbar), "h"((uint16_t)0x3) : "memory");
}

// arrive (cluster-scope, release) on target rank's mbarrier at same offset
__device__ __forceinline__ void mbar_arrive_rank(uint32_t addr, int trank) {
    asm volatile(
        "{\n\t.reg .b32 ra;\n\t"
        "mapa.shared::cluster.u32 ra, %0, %1;\n\t"
        "mbarrier.arrive.shared::cluster.b64 _, [ra];\n\t}"
        :: "r"(addr), "r"(trank) : "memory");
}

// DSMEM read of a b32 from target rank's smem at same offset
__device__ __forceinline__ uint32_t ld_dsmem_u32(uint32_t addr, int trank) {
    uint32_t v;
    asm volatile(
        "{\n\t.reg .b32 ra;\n\t"
        "mapa.shared::cluster.u32 ra, %1, %2;\n\t"
        "ld.shared::cluster.b32 %0, [ra];\n\t}"
        : "=r"(v) : "r"(addr), "r"(trank) : "memory");
    return v;
}

#define TC_LD_X32(r, tmem_addr) \
    asm volatile( \
        "tcgen05.ld.sync.aligned.32x32b.x32.b32 " \
        "{%0, %1, %2, %3, %4, %5, %6, %7, " \
        " %8, %9, %10, %11, %12, %13, %14, %15, " \
        " %16, %17, %18, %19, %20, %21, %22, %23, " \
        " %24, %25, %26, %27, %28, %29, %30, %31}, [%32];" \
        : "=r"((r)[0]),  "=r"((r)[1]),  "=r"((r)[2]),  "=r"((r)[3]), \
          "=r"((r)[4]),  "=r"((r)[5]),  "=r"((r)[6]),  "=r"((r)[7]), \
          "=r"((r)[8]),  "=r"((r)[9]),  "=r"((r)[10]), "=r"((r)[11]), \
          "=r"((r)[12]), "=r"((r)[13]), "=r"((r)[14]), "=r"((r)[15]), \
          "=r"((r)[16]), "=r"((r)[17]), "=r"((r)[18]), "=r"((r)[19]), \
          "=r"((r)[20]), "=r"((r)[21]), "=r"((r)[22]), "=r"((r)[23]), \
          "=r"((r)[24]), "=r"((r)[25]), "=r"((r)[26]), "=r"((r)[27]), \
          "=r"((r)[28]), "=r"((r)[29]), "=r"((r)[30]), "=r"((r)[31]) \
        : "r"(tmem_addr))

#define CLUSTER_SYNC_() do { \
    asm volatile("barrier.cluster.arrive.aligned;" ::: "memory"); \
    asm volatile("barrier.cluster.wait.aligned;" ::: "memory"); \
} while (0)
#endif  // HAVE_TCGEN05

// ============================================================================
// Persistent GEMM kernel: 74 cg2 pairs steal units u (mp = u&15, nt = u>>4)
// from the global ticket until exhausted.
// ============================================================================
__global__ void __launch_bounds__(192, 1) __cluster_dims__(2, 1, 1) qlinear_tc(
    const __grid_constant__ CUtensorMap tmAh,
    const __grid_constant__ CUtensorMap tmAl,
    const __grid_constant__ CUtensorMap tmB,
    const float* __restrict__ scales,
    const float* __restrict__ zps,
    const float* __restrict__ biasv,
    const float* __restrict__ rowsum,
    const float* __restrict__ rscale,
    float* __restrict__ out)
{
#if HAVE_TCGEN05
    extern __shared__ __align__(1024) char smem[];
    const uint32_t sb = smem_u32(smem);
    const int tid  = threadIdx.x;
    const int wid  = tid >> 5;
    const int lane = tid & 31;
    const int rank = blockIdx.x & 1;           // cg2 pair rank

    if (wid == 0) {
        asm volatile("tcgen05.alloc.cta_group::2.sync.aligned.shared::cta.b32 [%0], %1;"
                     :: "r"(sb + OFF_TMEM), "r"(512u) : "memory");
        asm volatile("tcgen05.relinquish_alloc_permit.cta_group::2.sync.aligned;");
    }
    if (tid == 0) {
        for (int s = 0; s < NST; s++) {
            MBAR_INIT(sb + OFF_FULL(s), 1);
            MBAR_INIT(sb + OFF_EMPTY(s), 1);
        }
        MBAR_INIT(sb + OFF_DONE, 1);
        MBAR_INIT(sb + OFF_EPIF, 2);      // one arrive per CTA's epilogue
        MBAR_INIT(sb + OFF_UNITB(0), 1);  // unit publication (leader-producer)
        MBAR_INIT(sb + OFF_UNITB(1), 1);
        MBAR_INIT(sb + OFF_URD(0), 4);    // slot-reuse guard: 4 readers
        MBAR_INIT(sb + OFF_URD(1), 4);
        asm volatile("fence.proxy.async.shared::cta;" ::: "memory");
    }
    __syncthreads();
    CLUSTER_SYNC_();   // peer barriers must be live before cg2 TMA / commits

    uint32_t tmem;
    asm volatile("ld.shared.b32 %0, [%1];" : "=r"(tmem) : "r"(sb + OFF_TMEM));

    // ---------------- producer warp (warp 4, lane 0, BOTH CTAs) ----------------
    if (wid == 4 && lane == 0) {
        int s = 0, k = 0;
        for (int j = 0;; j++) {
            int u;
            if (rank == 0) {
                if (j >= 2) mbar_wait_cl(sb + OFF_URD(j & 1), ((j >> 1) + 1) & 1);
                u = atomicAdd(&g_ticket, 1);
                if (u >= NUNIT) u = -1;
                *(volatile int*)(smem + OFF_UINFO(j & 1)) = u;
                mbar_arrive_rank(sb + OFF_UNITB(j & 1), 0);   // release (self)
                mbar_arrive_rank(sb + OFF_UNITB(j & 1), 1);   // release (peer)
            } else {
                mbar_wait_cl(sb + OFF_UNITB(j & 1), (j >> 1) & 1);
                u = (int)ld_dsmem_u32(sb + OFF_UINFO(j & 1), 0);
                mbar_arrive_rank(sb + OFF_URD(j & 1), 0);     // reader done
            }
            if (u < 0) break;
            const int rb = (u & 15) * 256 + rank * 128;       // A rows
            const int cb = (u >> 4) * 256 + rank * 128;       // B rows
            for (int c = 0; c < NCH; c++) {
                if (k > 0) mbar_wait_relaxed(sb + OFF_EMPTY(s), (k - 1) & 1);
                if (rank == 0) MBAR_EXPECT(sb + OFF_FULL(s), 2u * STAGE_STRIDE);
                const uint32_t st = sb + OFF_ST(s);
                const uint32_t fb = sb + OFF_FULL(s);
                tma_ld_cg2(st + ST_AH, &tmAh, c * KC, rb, fb);
                tma_ld_cg2(st + ST_AL, &tmAl, c * KC, rb, fb);
                tma_ld_cg2(st + ST_B,  &tmB,  c * KC, cb, fb);
                if (++s == NST) { s = 0; k++; }
            }
        }
    }

    // ---------------- MMA driver (leader CTA, warp 5, lane 0) ----------------
    if (rank == 0 && wid == 5 && lane == 0) {
        int s = 0, k = 0;
        for (int j = 0;; j++) {
            mbar_wait_cl(sb + OFF_UNITB(j & 1), (j >> 1) & 1);
            const int u = *(volatile int*)(smem + OFF_UINFO(j & 1));
            mbar_arrive_rank(sb + OFF_URD(j & 1), 0);
            if (u < 0) break;
            if (j > 0) {   // both CTAs' epilogues must have DRAINED unit j-1
                mbar_wait(sb + OFF_EPIF, (j - 1) & 1);
                asm volatile("tcgen05.fence::after_thread_sync;" ::: "memory");
            }
            for (int c = 0; c < NCH; c++) {
                mbar_wait_relaxed(sb + OFF_FULL(s), k & 1);
                const uint32_t st = sb + OFF_ST(s);
                const uint64_t ah = mk_desc64(st + ST_AH);
                const uint64_t al = mk_desc64(st + ST_AL);
                const uint64_t bd = mk_desc64(st + ST_B);
                const uint32_t en0 = (c > 0) ? 1u : 0u;
                mma_i8_ss_cg2(tmem,       ah,     bd,     MMA_IDESC, en0);
                mma_i8_ss_cg2(tmem,       ah + 2, bd + 2, MMA_IDESC, 1u);
                mma_i8_ss_cg2(tmem + 256, al,     bd,     MMA_IDESC, en0);
                mma_i8_ss_cg2(tmem + 256, al + 2, bd + 2, MMA_IDESC, 1u);
                tc_commit_mc2(sb + OFF_EMPTY(s));
                if (c == NCH - 1) tc_commit_mc2(sb + OFF_DONE);
                if (++s == NST) { s = 0; k++; }
            }
        }
    }

    // ---------------- epilogue warps (warps 0-3, BOTH CTAs) ----------------
    if (wid < 4) {
        float* s_sc = (float*)(smem + OFF_PRM);
        float* s_zp = s_sc + BN;
        float* s_bi = s_zp + BN;
        for (int j = 0;; j++) {
            mbar_wait_cl(sb + OFF_UNITB(j & 1), (j >> 1) & 1);
            int u;
            if (rank == 0) u = *(volatile int*)(smem + OFF_UINFO(j & 1));
            else           u = (int)ld_dsmem_u32(sb + OFF_UINFO(j & 1), 0);
            if (u < 0) break;
            const int cb  = (u >> 4) * 256;
            const int row = (u & 15) * 256 + rank * 128 + wid * 32 + lane;
            for (int i = tid; i < BN; i += 128) {
                s_sc[i] = scales[cb + i];
                s_zp[i] = zps[cb + i];
                s_bi[i] = biasv[cb + i];
            }
            asm volatile("bar.sync 1, 128;" ::: "memory");
            if (tid == 0) mbar_arrive_rank(sb + OFF_URD(j & 1), 0);  // reader done

            mbar_wait(sb + OFF_DONE, j & 1);
            asm volatile("tcgen05.fence::after_thread_sync;" ::: "memory");

            const float rs  = rowsum[row];
            const float srw = rscale[row];
            float* orow = out + (size_t)row * OUT_F + cb;

            // double-buffered TMEM drain; EPIF released right after last read
            uint32_t r1a[32], r0a[32], r1b[32], r0b[32];
            TC_LD_X32(r1a, tmem);
            TC_LD_X32(r0a, tmem + 256);
#pragma unroll
            for (int blk = 0; blk < 8; blk++) {
                asm volatile("tcgen05.wait::ld.sync.aligned;" ::: "memory");
                if (blk < 7) {
                    uint32_t* R1n = (blk & 1) ? r1a : r1b;
                    uint32_t* R0n = (blk & 1) ? r0a : r0b;
                    TC_LD_X32(R1n, tmem + (blk + 1) * 32);
                    TC_LD_X32(R0n, tmem + 256 + (blk + 1) * 32);
                } else {
                    asm volatile("tcgen05.fence::before_thread_sync;" ::: "memory");
                    asm volatile("bar.sync 2, 128;" ::: "memory");
                    if (tid == 0) mbar_arrive_rank(sb + OFF_EPIF, 0);
                }
                const uint32_t* R1 = (blk & 1) ? r1b : r1a;
                const uint32_t* R0 = (blk & 1) ? r0b : r0a;
#pragma unroll
                for (int c = 0; c < 32; c += 4) {
                    const int col = blk * 32 + c;
                    float4 v;
#pragma unroll
                    for (int jj = 0; jj < 4; jj++) {
                        const float acc = fmaf(128.f, (float)(int)R1[c + jj],
                                               (float)(int)R0[c + jj]);
                        (&v.x)[jj] = (srw * acc - s_zp[col + jj] * rs) * s_sc[col + jj]
                                     + s_bi[col + jj];
                    }
                    *reinterpret_cast<float4*>(orow + col) = v;
                }
            }
            asm volatile("bar.sync 1, 128;" ::: "memory");
        }
    }

    __syncthreads();
    CLUSTER_SYNC_();   // both CTAs done with TMEM before collective dealloc
    if (wid == 0) {
        asm volatile("tcgen05.dealloc.cta_group::2.sync.aligned.b32 %0, %1;"
                     :: "r"(tmem), "r"(512u));
    }
    CLUSTER_SYNC_();
#else
    (void)tmAh; (void)tmAl; (void)tmB; (void)scales; (void)zps; (void)biasv;
    (void)rowsum; (void)rscale; (void)out;
#endif
}

// ============================================================================
// Host launcher
// ============================================================================
typedef CUresult (*tme_fn_t)(CUtensorMap*, CUtensorMapDataType, cuuint32_t, void*,
                             const cuuint64_t*, const cuuint64_t*,
                             const cuuint32_t*, const cuuint32_t*,
                             CUtensorMapInterleave, CUtensorMapSwizzle,
                             CUtensorMapL2promotion, CUtensorMapFloatOOBfill);

extern "C" void kernel_launch(void* const* d_in, const int* in_sizes, int n_in,
                              void* d_out, int out_size) {
    const float* input  = (const float*)d_in[0];
    const int*   w      = (const int*)d_in[1];
    const float* scales = (const float*)d_in[2];
    const float* zps    = (const float*)d_in[3];
    const float* bias   = (const float*)d_in[4];
    float* out = (float*)d_out;
    (void)in_sizes; (void)n_in; (void)out_size;

    void *pW = nullptr, *pAh = nullptr, *pAl = nullptr, *pRs = nullptr, *pSc = nullptr;
    cudaGetSymbolAddress(&pW,  g_W8);
    cudaGetSymbolAddress(&pAh, g_Ah);
    cudaGetSymbolAddress(&pAl, g_Al);
    cudaGetSymbolAddress(&pRs, g_rowsum);
    cudaGetSymbolAddress(&pSc, g_rscale);

    tme_fn_t encode = nullptr;
    cudaDriverEntryPointQueryResult qr;
    cudaGetDriverEntryPoint("cuTensorMapEncodeTiled", (void**)&encode,
                            cudaEnableDefault, &qr);

    CUtensorMap mAh, mAl, mB;
    __builtin_memset(&mAh, 0, sizeof(mAh));
    __builtin_memset(&mAl, 0, sizeof(mAl));
    __builtin_memset(&mB, 0, sizeof(mB));
    if (encode) {
        {
            cuuint64_t dims[3]    = { IN_F, TOKENS, 1 };
            cuuint64_t strides[2] = { IN_F, (cuuint64_t)IN_F * TOKENS };
            cuuint32_t box[3]     = { KC, 128, 1 };    // 64B rows (SW64)
            cuuint32_t es[3]      = { 1, 1, 1 };
            encode(&mAh, CU_TENSOR_MAP_DATA_TYPE_UINT8, 3, pAh, dims, strides, box, es,
                   CU_TENSOR_MAP_INTERLEAVE_NONE, CU_TENSOR_MAP_SWIZZLE_64B,
                   CU_TENSOR_MAP_L2_PROMOTION_L2_128B, CU_TENSOR_MAP_FLOAT_OOB_FILL_NONE);
            encode(&mAl, CU_TENSOR_MAP_DATA_TYPE_UINT8, 3, pAl, dims, strides, box, es,
                   CU_TENSOR_MAP_INTERLEAVE_NONE, CU_TENSOR_MAP_SWIZZLE_64B,
                   CU_TENSOR_MAP_L2_PROMOTION_L2_128B, CU_TENSOR_MAP_FLOAT_OOB_FILL_NONE);
        }
        {
            cuuint64_t dims[3]    = { IN_F, OUT_F, 1 };
            cuuint64_t strides[2] = { IN_F, (cuuint64_t)IN_F * OUT_F };
            cuuint32_t box[3]     = { KC, 128, 1 };    // 128-row pieces per CTA
            cuuint32_t es[3]      = { 1, 1, 1 };
            encode(&mB, CU_TENSOR_MAP_DATA_TYPE_UINT8, 3, pW, dims, strides, box, es,
                   CU_TENSOR_MAP_INTERLEAVE_NONE, CU_TENSOR_MAP_SWIZZLE_64B,
                   CU_TENSOR_MAP_L2_PROMOTION_L2_128B, CU_TENSOR_MAP_FLOAT_OOB_FILL_NONE);
        }
    }

    cudaFuncSetAttribute(qlinear_tc, cudaFuncAttributeMaxDynamicSharedMemorySize,
                         SMEM_TOTAL);

    // fused preprocessing: W pack + x two-digit quantization + ticket reset
    k_prep<<<NBLK_W + TOKENS, 256>>>((const int4*)w, (char4*)pW,
                                     (const float4*)input, (char4*)pAh, (char4*)pAl,
                                     (float*)pRs, (float*)pSc);

    // persistent GEMM: 148 CTAs = 74 cg2 pairs, dynamic work-stealing
    qlinear_tc<<<dim3(2 * NPAIR, 1), 192, SMEM_TOTAL>>>(
        mAh, mAl, mB, scales, zps, bias,
        (const float*)pRs, (const float*)pSc, out);
}